// round 14
// baseline (speedup 1.0000x reference)
#include <cuda_runtime.h>
#include <cstdint>

// ---------------------------------------------------------------------------
// out[8192,1000] = sign(X) @ sign(W)^T via bit-packing + XOR+POPC.
// dot = D - 2*popc(a^b). R2 compute loop (proven op-mix optimum) + cp.async
// double-buffer + NEW: split-K=4. 512 CTAs @ occ2 = 1.73 waves quantized to
// 2.0; split-K gives 2048 CTAs -> 6.92 -> 7 quarter-waves = 1.75 waves.
// Partial sums land via atomicAdd (fp32 exact for integers < 2^24); output
// zeroed by cudaMemsetAsync (graph-capturable).
// ---------------------------------------------------------------------------
#define M_DIM 8192
#define N_DIM 1000
#define NP    1024
#define D_DIM 12288
#define KW    384            // 32-bit words per row
#define NSPLIT 4
#define KSPW  (KW / NSPLIT)  // 96 words per split
#define KCW   32             // words per K-chunk
#define NCH   (KSPW / KCW)   // 3 chunks per split
#define RSB   144            // smem row stride bytes (36 words, conflict-free)
#define TILE_B   (128 * RSB)            // 18432 B per operand tile
#define STAGE_B  (2 * TILE_B)           // 36864 B (A + B)
#define SMEM_REQ (2 * STAGE_B)          // 73728 B (2 stages) -> 2 CTAs/SM

__device__ uint32_t g_bitsA[(size_t)M_DIM * KW];   // 12.6 MB
__device__ uint32_t g_bitsW[(size_t)NP * KW];      // 1.6 MB (pad rows zero)

// ============================ helpers ======================================
__device__ __forceinline__ uint32_t smem_to_u32(const void* p) {
    uint32_t a;
    asm("{ .reg .u64 t; cvta.to.shared.u64 t, %1; cvt.u32.u64 %0, t; }"
        : "=r"(a) : "l"(p));
    return a;
}
__device__ __forceinline__ void cp_async16(uint32_t saddr, const void* gptr) {
    asm volatile("cp.async.cg.shared.global [%0], [%1], 16;"
                 :: "r"(saddr), "l"(gptr));
}
#define CP_COMMIT() asm volatile("cp.async.commit_group;" ::: "memory")
#define CP_WAIT(n)  asm volatile("cp.async.wait_group %0;" :: "n"(n) : "memory")

// =========================== pack kernels ==================================
// MLP=16 pack (R12-proven: 82.8% DRAM): 16 independent 128B loads per warp
// iteration, then 16 ballots, lanes 0-3 store uint4 each.
__global__ __launch_bounds__(256)
void pack_sign_A(const float* __restrict__ in, uint32_t* __restrict__ out,
                 int nwords) {
    int warp_id = (blockIdx.x * blockDim.x + threadIdx.x) >> 5;
    int lane    = threadIdx.x & 31;
    int w0 = warp_id * 16;
    if (w0 >= nwords) return;
    const float* base = in + (size_t)w0 * 32 + lane;
    float v[16];
#pragma unroll
    for (int c = 0; c < 16; c++) v[c] = base[c * 32];
    uint32_t w[16];
#pragma unroll
    for (int c = 0; c < 16; c++)
        w[c] = __ballot_sync(0xffffffffu, v[c] > 0.0f);
    if (lane < 4) {
        *reinterpret_cast<uint4*>(out + w0 + lane * 4) =
            make_uint4(w[lane * 4], w[lane * 4 + 1],
                       w[lane * 4 + 2], w[lane * 4 + 3]);
    }
}

__global__ __launch_bounds__(256)
void pack_sign_W(const float* __restrict__ in, uint32_t* __restrict__ out) {
    int warp_id = (blockIdx.x * blockDim.x + threadIdx.x) >> 5;
    int lane    = threadIdx.x & 31;
    int w0 = warp_id * 4;
    if (w0 >= NP * KW) return;
    int row = w0 / KW;
    uint32_t w[4] = {0u, 0u, 0u, 0u};
    if (row < N_DIM) {
        const float* base = in + (size_t)w0 * 32;
#pragma unroll
        for (int c = 0; c < 4; c++)
            w[c] = __ballot_sync(0xffffffffu, base[c * 32 + lane] > 0.0f);
    }
    if (lane == 0)
        *reinterpret_cast<uint4*>(out + w0) = make_uint4(w[0], w[1], w[2], w[3]);
}

// ============================== GEMM =======================================
// 128x128 tile x K-quarter, 256 threads, 8x8 micro-tile (R2 compute loop).
__global__ __launch_bounds__(256, 2)
void bgemm_popc_kernel(const uint32_t* __restrict__ Ab,
                       const uint32_t* __restrict__ Wb,
                       float* __restrict__ out)
{
    extern __shared__ char smem[];
    const uint32_t sbase = smem_to_u32(smem);
    const int tid = threadIdx.x;
    const int tx  = tid & 15;
    const int ty  = tid >> 4;
    const int mBase = blockIdx.y * 128;
    const int nBase = blockIdx.x * 128;
    const int kOff  = blockIdx.z * KSPW;     // word offset of this K split

    int acc[8][8];
#pragma unroll
    for (int i = 0; i < 8; i++)
#pragma unroll
        for (int j = 0; j < 8; j++) acc[i][j] = 0;

    // --- stage loader: A/B 128 rows x 32 words, 16B cp.async units ---------
    auto load_stage = [&](int stage, int chunk) {
        const uint32_t sA = sbase + stage * STAGE_B;
        const uint32_t sB = sA + TILE_B;
        const int kw = kOff + chunk * KCW;
#pragma unroll
        for (int l = 0; l < 4; l++) {
            int u = tid + l * 256;
            int row = u >> 3, c = u & 7;
            uint32_t d = (uint32_t)(row * RSB + c * 16);
            cp_async16(sA + d, Ab + (size_t)(mBase + row) * KW + kw + c * 4);
            cp_async16(sB + d, Wb + (size_t)(nBase + row) * KW + kw + c * 4);
        }
    };

    // --- compute one 32-word chunk (R2 loop: popc-sum, IADD3 tree) ----------
    auto compute_stage = [&](int stage) {
        const char* cA = smem + stage * STAGE_B;
        const char* cB = cA + TILE_B;
#pragma unroll
        for (int k = 0; k < KCW; k += 4) {
            uint4 b4[8];
#pragma unroll
            for (int j = 0; j < 8; j++)
                b4[j] = *reinterpret_cast<const uint4*>(
                    cB + (tx + 16 * j) * RSB + k * 4);
#pragma unroll
            for (int i = 0; i < 8; i++) {
                uint4 a4 = *reinterpret_cast<const uint4*>(
                    cA + (ty + 16 * i) * RSB + k * 4);
#pragma unroll
                for (int j = 0; j < 8; j++) {
                    acc[i][j] += __popc(a4.x ^ b4[j].x) + __popc(a4.y ^ b4[j].y)
                               + __popc(a4.z ^ b4[j].z) + __popc(a4.w ^ b4[j].w);
                }
            }
        }
    };

    // --- 2-stage cp.async pipeline over 3 chunks ----------------------------
    load_stage(0, 0); CP_COMMIT();
    for (int i = 0; i < NCH; i++) {
        if (i + 1 < NCH) load_stage((i + 1) & 1, i + 1);
        CP_COMMIT();
        CP_WAIT(1);
        __syncthreads();
        compute_stage(i & 1);
        __syncthreads();
    }

    // --- epilogue: partial dot = KSPW*32 - 2*mismatches, atomic-accumulate --
    const float dterm = (float)(KSPW * 32);
#pragma unroll
    for (int i = 0; i < 8; i++) {
        int m = mBase + ty + 16 * i;
#pragma unroll
        for (int j = 0; j < 8; j++) {
            int n = nBase + tx + 16 * j;
            if (n < N_DIM)
                atomicAdd(out + (size_t)m * N_DIM + n,
                          dterm - 2.0f * (float)acc[i][j]);
        }
    }
}

// =============================== launcher ==================================
extern "C" void kernel_launch(void* const* d_in, const int* in_sizes, int n_in,
                              void* d_out, int out_size) {
    const float* inp = (const float*)d_in[0];   // [8192, 12288]
    const float* wt  = (const float*)d_in[1];   // [1000, 12288]
    float* out = (float*)d_out;                 // [8192, 1000]

    uint32_t* bitsA = nullptr;
    uint32_t* bitsW = nullptr;
    cudaGetSymbolAddress((void**)&bitsA, g_bitsA);
    cudaGetSymbolAddress((void**)&bitsW, g_bitsW);

    {   // pack A (MLP=16)
        int nwords = M_DIM * KW;                // 3,145,728
        int warps  = nwords / 16;
        int blocks = (warps * 32 + 255) / 256;
        pack_sign_A<<<blocks, 256>>>(inp, bitsA, nwords);
    }
    {   // pack W padded to 1024 rows
        int nwords = NP * KW;
        int blocks = (nwords / 4 * 32 + 255) / 256;
        pack_sign_W<<<blocks, 256>>>(wt, bitsW);
    }

    // zero output for atomic accumulation (graph-capturable memset node)
    cudaMemsetAsync(out, 0, (size_t)out_size * sizeof(float));

    static bool attr_set = false;
    if (!attr_set) {
        cudaFuncSetAttribute(bgemm_popc_kernel,
                             cudaFuncAttributeMaxDynamicSharedMemorySize, SMEM_REQ);
        attr_set = true;
    }
    // grid: x = N tiles (8), y = M tiles (64), z = K splits (4) -> 2048 CTAs
    dim3 grid(NP / 128, M_DIM / 128, NSPLIT);
    bgemm_popc_kernel<<<grid, 256, SMEM_REQ>>>(bitsA, bitsW, out);
}

// round 16
// speedup vs baseline: 1.5198x; 1.5198x over previous
#include <cuda_runtime.h>
#include <cstdint>

// ---------------------------------------------------------------------------
// out[8192,1000] = sign(X) @ sign(W)^T via bit-packing + XOR+POPC.
// dot = D - 2*popc(a^b). R2 compute formulation (proven op-mix optimum),
// cp.async double-buffer, MLP=16 pack. R14 post-mortem: split-K atomics cost
// >> tail savings. This round fixes the tail atomic-free: 64x64 tiles ->
// 2048 CTAs -> 13.84 tiles/SM -> ceil 14 -> 98.8% utilization (vs 512 tiles
// -> 3.46 -> 4 -> 86.5%). alu inst count is tiling-invariant.
// ---------------------------------------------------------------------------
#define M_DIM 8192
#define N_DIM 1000
#define NP    1024
#define D_DIM 12288
#define KW    384            // 32-bit words per row
#define KCW   32             // words per K-chunk
#define NCH   12             // KW / KCW
#define TT    64             // tile dim (M and N)
#define RSB   144            // smem row stride bytes (36 words, conflict-free)
#define TILE_B   (TT * RSB)             // 9216 B per operand tile
#define STAGE_B  (2 * TILE_B)           // 18432 B (A + B)
#define SMEM_REQ (2 * STAGE_B)          // 36864 B (2 stages)

__device__ uint32_t g_bitsA[(size_t)M_DIM * KW];   // 12.6 MB
__device__ uint32_t g_bitsW[(size_t)NP * KW];      // 1.6 MB (pad rows zero)

// ============================ helpers ======================================
__device__ __forceinline__ void cp_async16(uint32_t saddr, const void* gptr) {
    asm volatile("cp.async.cg.shared.global [%0], [%1], 16;"
                 :: "r"(saddr), "l"(gptr));
}
__device__ __forceinline__ uint32_t smem_to_u32(const void* p) {
    uint32_t a;
    asm("{ .reg .u64 t; cvta.to.shared.u64 t, %1; cvt.u32.u64 %0, t; }"
        : "=r"(a) : "l"(p));
    return a;
}
#define CP_COMMIT() asm volatile("cp.async.commit_group;" ::: "memory")
#define CP_WAIT(n)  asm volatile("cp.async.wait_group %0;" :: "n"(n) : "memory")

// =========================== pack kernels ==================================
// MLP=16 pack (R12-proven: ~82% DRAM): 16 independent coalesced 128B loads
// per warp iteration, 16 ballots, lanes 0-3 store one uint4 each.
__global__ __launch_bounds__(256)
void pack_sign_A(const float* __restrict__ in, uint32_t* __restrict__ out,
                 int nwords) {
    int warp_id = (blockIdx.x * blockDim.x + threadIdx.x) >> 5;
    int lane    = threadIdx.x & 31;
    int w0 = warp_id * 16;
    if (w0 >= nwords) return;
    const float* base = in + (size_t)w0 * 32 + lane;
    float v[16];
#pragma unroll
    for (int c = 0; c < 16; c++) v[c] = base[c * 32];
    uint32_t w[16];
#pragma unroll
    for (int c = 0; c < 16; c++)
        w[c] = __ballot_sync(0xffffffffu, v[c] > 0.0f);
    if (lane < 4) {
        *reinterpret_cast<uint4*>(out + w0 + lane * 4) =
            make_uint4(w[lane * 4], w[lane * 4 + 1],
                       w[lane * 4 + 2], w[lane * 4 + 3]);
    }
}

__global__ __launch_bounds__(256)
void pack_sign_W(const float* __restrict__ in, uint32_t* __restrict__ out) {
    int warp_id = (blockIdx.x * blockDim.x + threadIdx.x) >> 5;
    int lane    = threadIdx.x & 31;
    int w0 = warp_id * 4;
    if (w0 >= NP * KW) return;
    int row = w0 / KW;
    uint32_t w[4] = {0u, 0u, 0u, 0u};
    if (row < N_DIM) {
        const float* base = in + (size_t)w0 * 32;
#pragma unroll
        for (int c = 0; c < 4; c++)
            w[c] = __ballot_sync(0xffffffffu, base[c * 32 + lane] > 0.0f);
    }
    if (lane == 0)
        *reinterpret_cast<uint4*>(out + w0) = make_uint4(w[0], w[1], w[2], w[3]);
}

// ============================== GEMM =======================================
// 64x64 tile, 256 threads, 4x4 micro-tile per thread.
// Thread (tx,ty): rows m = mBase + ty + 16*i (i<4), cols n = nBase + tx + 16*j.
__global__ __launch_bounds__(256)
void bgemm_popc_kernel(const uint32_t* __restrict__ Ab,
                       const uint32_t* __restrict__ Wb,
                       float* __restrict__ out)
{
    extern __shared__ char smem[];
    const uint32_t sbase = smem_to_u32(smem);
    const int tid = threadIdx.x;
    const int tx  = tid & 15;
    const int ty  = tid >> 4;
    const int mBase = blockIdx.y * TT;
    const int nBase = blockIdx.x * TT;

    int acc[4][4];
#pragma unroll
    for (int i = 0; i < 4; i++)
#pragma unroll
        for (int j = 0; j < 4; j++) acc[i][j] = 0;

    // --- stage loader: A/B 64 rows x 32 words = 512 uint4 units each --------
    auto load_stage = [&](int stage, int chunk) {
        const uint32_t sA = sbase + stage * STAGE_B;
        const uint32_t sB = sA + TILE_B;
        const int kw = chunk * KCW;
#pragma unroll
        for (int l = 0; l < 2; l++) {           // 2 units per thread, each op
            int u = tid + l * 256;
            int row = u >> 3, c = u & 7;
            uint32_t d = (uint32_t)(row * RSB + c * 16);
            cp_async16(sA + d, Ab + (size_t)(mBase + row) * KW + kw + c * 4);
            cp_async16(sB + d, Wb + (size_t)(nBase + row) * KW + kw + c * 4);
        }
    };

    // --- compute one 32-word chunk (R2 loop: popc-sum, IADD3 tree) ----------
    auto compute_stage = [&](int stage) {
        const char* cA = smem + stage * STAGE_B;
        const char* cB = cA + TILE_B;
#pragma unroll
        for (int k = 0; k < KCW; k += 4) {
            uint4 b4[4];
#pragma unroll
            for (int j = 0; j < 4; j++)
                b4[j] = *reinterpret_cast<const uint4*>(
                    cB + (tx + 16 * j) * RSB + k * 4);
#pragma unroll
            for (int i = 0; i < 4; i++) {
                uint4 a4 = *reinterpret_cast<const uint4*>(
                    cA + (ty + 16 * i) * RSB + k * 4);
#pragma unroll
                for (int j = 0; j < 4; j++) {
                    acc[i][j] += __popc(a4.x ^ b4[j].x) + __popc(a4.y ^ b4[j].y)
                               + __popc(a4.z ^ b4[j].z) + __popc(a4.w ^ b4[j].w);
                }
            }
        }
    };

    // --- 2-stage cp.async pipeline ------------------------------------------
    load_stage(0, 0); CP_COMMIT();
    for (int i = 0; i < NCH; i++) {
        if (i + 1 < NCH) load_stage((i + 1) & 1, i + 1);
        CP_COMMIT();
        CP_WAIT(1);
        __syncthreads();
        compute_stage(i & 1);
        __syncthreads();
    }

    // --- epilogue: dot = D - 2*mismatches; plain guarded stores -------------
#pragma unroll
    for (int i = 0; i < 4; i++) {
        int m = mBase + ty + 16 * i;
#pragma unroll
        for (int j = 0; j < 4; j++) {
            int n = nBase + tx + 16 * j;
            if (n < N_DIM)
                out[(size_t)m * N_DIM + n] = (float)(D_DIM - 2 * acc[i][j]);
        }
    }
}

// =============================== launcher ==================================
extern "C" void kernel_launch(void* const* d_in, const int* in_sizes, int n_in,
                              void* d_out, int out_size) {
    const float* inp = (const float*)d_in[0];   // [8192, 12288]
    const float* wt  = (const float*)d_in[1];   // [1000, 12288]
    float* out = (float*)d_out;                 // [8192, 1000]

    uint32_t* bitsA = nullptr;
    uint32_t* bitsW = nullptr;
    cudaGetSymbolAddress((void**)&bitsA, g_bitsA);
    cudaGetSymbolAddress((void**)&bitsW, g_bitsW);

    {   // pack A (MLP=16)
        int nwords = M_DIM * KW;                // 3,145,728
        int warps  = nwords / 16;
        int blocks = (warps * 32 + 255) / 256;
        pack_sign_A<<<blocks, 256>>>(inp, bitsA, nwords);
    }
    {   // pack W padded to 1024 rows
        int nwords = NP * KW;
        int blocks = (nwords / 4 * 32 + 255) / 256;
        pack_sign_W<<<blocks, 256>>>(wt, bitsW);
    }

    static bool attr_set = false;
    if (!attr_set) {
        cudaFuncSetAttribute(bgemm_popc_kernel,
                             cudaFuncAttributeMaxDynamicSharedMemorySize, SMEM_REQ);
        attr_set = true;
    }
    // 2048 tiles of 64x64: 13.84 tiles/SM -> 98.8% quantization efficiency.
    // x = N tiles (16, fastest -> A-tile L2 reuse), y = M tiles (128).
    dim3 grid(NP / TT, M_DIM / TT);
    bgemm_popc_kernel<<<grid, 256, SMEM_REQ>>>(bitsA, bitsW, out);
}